// round 8
// baseline (speedup 1.0000x reference)
#include <cuda_runtime.h>

// Fixed shapes: B=8, H=8, S=16384, Dv=64, d_k=1
#define BH      64
#define SEQ     16384
#define DV      64
#define NSPLIT  16
#define CHUNK   (SEQ / NSPLIT)     // 1024 rows per reduce item
#define PSTRIDE 68                 // 64 ktv + ksq + qsq, float4-aligned
#define NCTA    1024               // all co-resident (8/SM x 148 = 1184)
#define BROWS   256
#define BCHUNKS 4                  // 1024 CTAs x 4 x 256 rows = 1,048,576 rows

__device__ float g_part[BH * NSPLIT * PSTRIDE];
__device__ int   g_arrive;   // reduce-done barrier counter (self-resetting)
__device__ int   g_bdone;    // broadcast-done counter (resets both)

struct Smem {
    float  sK[CHUNK];             // reduce: K chunk; broadcast: Q slice [0,256)
    float4 s_acc[8][16];
    float  s_ksq[8];
    float  s_qsq[8];
    float  s_coef[DV];
    float  s_scale;
};

__global__ __launch_bounds__(256, 8) void fused_kernel(
    const float* __restrict__ Q,
    const float* __restrict__ K,
    const float* __restrict__ V,
    float* __restrict__ out)
{
    __shared__ Smem sm;
    const int c = blockIdx.x;
    const int t = threadIdx.x;
    const int colg = t & 15;
    const int rowg = t >> 4;

    // ============================ Phase 1: reduce ===========================
    {
        const int bh    = c / NSPLIT;
        const int split = c % NSPLIT;

        const float4* __restrict__ Vp4 =
            reinterpret_cast<const float4*>(V + (size_t)bh * SEQ * DV + (size_t)(split * CHUNK) * DV);
        const float4* __restrict__ Kp4 =
            reinterpret_cast<const float4*>(K + bh * SEQ + split * CHUNK);
        const float4* __restrict__ Qp4 =
            reinterpret_cast<const float4*>(Q + bh * SEQ + split * CHUNK);

        float4 kv = Kp4[t];
        reinterpret_cast<float4*>(sm.sK)[t] = kv;
        float ksq = kv.x * kv.x + kv.y * kv.y + kv.z * kv.z + kv.w * kv.w;
        float4 qv = Qp4[t];
        float qsq = qv.x * qv.x + qv.y * qv.y + qv.z * qv.z + qv.w * qv.w;
        __syncthreads();

        float4 a0 = make_float4(0.f, 0.f, 0.f, 0.f);
        float4 a1 = make_float4(0.f, 0.f, 0.f, 0.f);

        #pragma unroll 4
        for (int r = rowg; r < CHUNK; r += 32) {
            float  k0 = sm.sK[r];
            float4 v0 = __ldcs(&Vp4[(size_t)r * 16 + colg]);
            float  k1 = sm.sK[r + 16];
            float4 v1 = __ldcs(&Vp4[(size_t)(r + 16) * 16 + colg]);
            a0.x += k0 * v0.x;  a0.y += k0 * v0.y;  a0.z += k0 * v0.z;  a0.w += k0 * v0.w;
            a1.x += k1 * v1.x;  a1.y += k1 * v1.y;  a1.z += k1 * v1.z;  a1.w += k1 * v1.w;
        }
        a0.x += a1.x; a0.y += a1.y; a0.z += a1.z; a0.w += a1.w;

        a0.x += __shfl_xor_sync(0xFFFFFFFFu, a0.x, 16);
        a0.y += __shfl_xor_sync(0xFFFFFFFFu, a0.y, 16);
        a0.z += __shfl_xor_sync(0xFFFFFFFFu, a0.z, 16);
        a0.w += __shfl_xor_sync(0xFFFFFFFFu, a0.w, 16);

        #pragma unroll
        for (int m = 16; m >= 1; m >>= 1) {
            ksq += __shfl_xor_sync(0xFFFFFFFFu, ksq, m);
            qsq += __shfl_xor_sync(0xFFFFFFFFu, qsq, m);
        }

        const int warp = t >> 5;
        const int lane = t & 31;
        if (lane < 16) sm.s_acc[warp][lane] = a0;
        if (lane == 0) { sm.s_ksq[warp] = ksq; sm.s_qsq[warp] = qsq; }
        __syncthreads();

        float* __restrict__ outp = g_part + (size_t)(bh * NSPLIT + split) * PSTRIDE;
        if (t < 16) {
            float4 a = sm.s_acc[0][t];
            #pragma unroll
            for (int w = 1; w < 8; ++w) {
                float4 b = sm.s_acc[w][t];
                a.x += b.x; a.y += b.y; a.z += b.z; a.w += b.w;
            }
            reinterpret_cast<float4*>(outp)[t] = a;
        } else if (t == 16) {
            float a = 0.f, b = 0.f;
            #pragma unroll
            for (int w = 0; w < 8; ++w) { a += sm.s_ksq[w]; b += sm.s_qsq[w]; }
            outp[64] = a;
            outp[65] = b;
        }
    }

    // ====================== Grid barrier (all resident) =====================
    __threadfence();
    __syncthreads();
    if (t == 0) {
        atomicAdd(&g_arrive, 1);
        while (((volatile int*)&g_arrive)[0] < NCTA) __nanosleep(256);
        __threadfence();
    }
    __syncthreads();

    // =========================== Phase 2: broadcast =========================
    {
        const int bh = c >> 4;   // CTA c writes rows [c*1024, (c+1)*1024), bh = c/16

        // Combine partials -> coef once per CTA (same order as before).
        const float* __restrict__ base = g_part + (size_t)bh * NSPLIT * PSTRIDE;
        if (t < DV) {
            float ktv = 0.f;
            #pragma unroll
            for (int s = 0; s < NSPLIT; ++s) ktv += base[(size_t)s * PSTRIDE + t];
            sm.s_coef[t] = ktv;
        } else if (t == DV) {
            float ksq = 0.f, qsq = 0.f;
            #pragma unroll
            for (int s = 0; s < NSPLIT; ++s) {
                ksq += base[(size_t)s * PSTRIDE + 64];
                qsq += base[(size_t)s * PSTRIDE + 65];
            }
            sm.s_scale = 1.0f / (sqrtf(ksq) * sqrtf(qsq));
        }
        __syncthreads();

        const int rg = t >> 4;
        const int cg = t & 15;
        const float scale = sm.s_scale;
        float4 c4 = reinterpret_cast<const float4*>(sm.s_coef)[cg];
        c4.x *= scale; c4.y *= scale; c4.z *= scale; c4.w *= scale;
        __syncthreads();   // coef in regs before sK reuse

        const size_t base_row = (size_t)c * (BCHUNKS * BROWS);

        #pragma unroll 1
        for (int ch = 0; ch < BCHUNKS; ++ch) {
            const size_t row0 = base_row + (size_t)ch * BROWS;
            sm.sK[t] = Q[row0 + t];
            __syncthreads();
            #pragma unroll
            for (int ri = 0; ri < BROWS / 16; ++ri) {
                const int    lr  = ri * 16 + rg;
                const size_t row = row0 + lr;
                const float  q   = sm.sK[lr];
                float4 o;
                o.x = q * c4.x;
                o.y = q * c4.y;
                o.z = q * c4.z;
                o.w = q * c4.w;
                __stcs(reinterpret_cast<float4*>(out) + row * 16 + cg, o);
            }
            __syncthreads();
        }
    }

    // Self-reset for graph replay: last CTA to finish clears both counters.
    if (t == 0) {
        int v = atomicAdd(&g_bdone, 1);
        if (v == NCTA - 1) {
            g_arrive = 0;
            g_bdone  = 0;
        }
    }
}

// ---------------------------------------------------------------------------
extern "C" void kernel_launch(void* const* d_in, const int* in_sizes, int n_in,
                              void* d_out, int out_size)
{
    const float* Q = (const float*)d_in[0];
    const float* K = (const float*)d_in[1];
    const float* V = (const float*)d_in[2];
    float* out = (float*)d_out;

    fused_kernel<<<NCTA, 256>>>(Q, K, V, out);
}

// round 9
// speedup vs baseline: 1.0646x; 1.0646x over previous
#include <cuda_runtime.h>

// Fixed shapes: B=8, H=8, S=16384, Dv=64, d_k=1
#define BH      64
#define SEQ     16384
#define DV      64
#define NSPLIT  16
#define CHUNK   (SEQ / NSPLIT)   // 1024 rows per split
#define PSTRIDE 68               // 64 ktv + ksq + qsq, padded to float4 stride

__device__ float g_part[BH * NSPLIT * PSTRIDE];

// ---------------------------------------------------------------------------
// Kernel 1: per-(bh, split) partial reduction. (proven: 44.2us @ 80% DRAM)
// ---------------------------------------------------------------------------
__global__ __launch_bounds__(256) void reduce_kernel(
    const float* __restrict__ Q,
    const float* __restrict__ K,
    const float* __restrict__ V)
{
    const int bh    = blockIdx.x / NSPLIT;
    const int split = blockIdx.x % NSPLIT;
    const int t     = threadIdx.x;
    const int colg  = t & 15;
    const int rowg  = t >> 4;

    const float4* __restrict__ Vp4 =
        reinterpret_cast<const float4*>(V + (size_t)bh * SEQ * DV + (size_t)(split * CHUNK) * DV);
    const float4* __restrict__ Kp4 =
        reinterpret_cast<const float4*>(K + bh * SEQ + split * CHUNK);
    const float4* __restrict__ Qp4 =
        reinterpret_cast<const float4*>(Q + bh * SEQ + split * CHUNK);

    __shared__ float sK[CHUNK];

    float4 kv = Kp4[t];
    reinterpret_cast<float4*>(sK)[t] = kv;
    float ksq = kv.x * kv.x + kv.y * kv.y + kv.z * kv.z + kv.w * kv.w;
    float4 qv = Qp4[t];
    float qsq = qv.x * qv.x + qv.y * qv.y + qv.z * qv.z + qv.w * qv.w;
    __syncthreads();

    float4 a0 = make_float4(0.f, 0.f, 0.f, 0.f);
    float4 a1 = make_float4(0.f, 0.f, 0.f, 0.f);

    #pragma unroll 4
    for (int r = rowg; r < CHUNK; r += 32) {
        float  k0 = sK[r];
        float4 v0 = __ldcs(&Vp4[(size_t)r * 16 + colg]);
        float  k1 = sK[r + 16];
        float4 v1 = __ldcs(&Vp4[(size_t)(r + 16) * 16 + colg]);
        a0.x += k0 * v0.x;  a0.y += k0 * v0.y;  a0.z += k0 * v0.z;  a0.w += k0 * v0.w;
        a1.x += k1 * v1.x;  a1.y += k1 * v1.y;  a1.z += k1 * v1.z;  a1.w += k1 * v1.w;
    }
    a0.x += a1.x; a0.y += a1.y; a0.z += a1.z; a0.w += a1.w;

    a0.x += __shfl_xor_sync(0xFFFFFFFFu, a0.x, 16);
    a0.y += __shfl_xor_sync(0xFFFFFFFFu, a0.y, 16);
    a0.z += __shfl_xor_sync(0xFFFFFFFFu, a0.z, 16);
    a0.w += __shfl_xor_sync(0xFFFFFFFFu, a0.w, 16);

    #pragma unroll
    for (int m = 16; m >= 1; m >>= 1) {
        ksq += __shfl_xor_sync(0xFFFFFFFFu, ksq, m);
        qsq += __shfl_xor_sync(0xFFFFFFFFu, qsq, m);
    }

    __shared__ float4 s_acc[8][16];
    __shared__ float  s_ksq[8];
    __shared__ float  s_qsq[8];
    const int warp = t >> 5;
    const int lane = t & 31;
    if (lane < 16) s_acc[warp][lane] = a0;
    if (lane == 0) { s_ksq[warp] = ksq; s_qsq[warp] = qsq; }
    __syncthreads();

    float* __restrict__ outp = g_part + (size_t)(bh * NSPLIT + split) * PSTRIDE;
    if (t < 16) {
        float4 a = s_acc[0][t];
        #pragma unroll
        for (int w = 1; w < 8; ++w) {
            float4 b = s_acc[w][t];
            a.x += b.x; a.y += b.y; a.z += b.z; a.w += b.w;
        }
        reinterpret_cast<float4*>(outp)[t] = a;
    } else if (t == 16) {
        float a = 0.f, b = 0.f;
        #pragma unroll
        for (int w = 0; w < 8; ++w) { a += s_ksq[w]; b += s_qsq[w]; }
        outp[64] = a;
        outp[65] = b;
    }
}

// ---------------------------------------------------------------------------
// Kernel 2 (fused combine + broadcast), now with __launch_bounds__(256, 8) to
// force <=32 regs -> 8 CTA/SM (64 warps) residency for a deeper store queue.
// ---------------------------------------------------------------------------
#define BROWS 256
__global__ __launch_bounds__(256, 8) void broadcast_kernel(
    const float* __restrict__ Q,
    float* __restrict__ out)
{
    const size_t row0 = (size_t)blockIdx.x * BROWS;  // 256 | 16384 -> single bh
    const int    t    = threadIdx.x;
    const int    bh   = (int)(row0 >> 14);

    __shared__ float s_coef[DV];
    __shared__ float s_scale;
    __shared__ float sQ[BROWS];

    sQ[t] = Q[row0 + t];

    const float* __restrict__ base = g_part + (size_t)bh * NSPLIT * PSTRIDE;
    if (t < DV) {
        float ktv = 0.f;
        #pragma unroll
        for (int s = 0; s < NSPLIT; ++s) ktv += base[(size_t)s * PSTRIDE + t];
        s_coef[t] = ktv;
    } else if (t == DV) {
        float ksq = 0.f, qsq = 0.f;
        #pragma unroll
        for (int s = 0; s < NSPLIT; ++s) {
            ksq += base[(size_t)s * PSTRIDE + 64];
            qsq += base[(size_t)s * PSTRIDE + 65];
        }
        s_scale = 1.0f / (sqrtf(ksq) * sqrtf(qsq));
    }
    __syncthreads();

    const int rg = t >> 4;
    const int cg = t & 15;
    const float scale = s_scale;
    float4 c = reinterpret_cast<const float4*>(s_coef)[cg];
    c.x *= scale; c.y *= scale; c.z *= scale; c.w *= scale;

    #pragma unroll
    for (int ri = 0; ri < BROWS / 16; ++ri) {
        const int    lr  = ri * 16 + rg;
        const size_t row = row0 + lr;
        const float  q   = sQ[lr];
        float4 o;
        o.x = q * c.x;
        o.y = q * c.y;
        o.z = q * c.z;
        o.w = q * c.w;
        __stcs(reinterpret_cast<float4*>(out) + row * 16 + cg, o);
    }
}

// ---------------------------------------------------------------------------
extern "C" void kernel_launch(void* const* d_in, const int* in_sizes, int n_in,
                              void* d_out, int out_size)
{
    const float* Q = (const float*)d_in[0];
    const float* K = (const float*)d_in[1];
    const float* V = (const float*)d_in[2];
    float* out = (float*)d_out;

    reduce_kernel<<<BH * NSPLIT, 256>>>(Q, K, V);
    broadcast_kernel<<<(BH * SEQ) / BROWS, 256>>>(Q, out);
}